// round 1
// baseline (speedup 1.0000x reference)
#include <cuda_runtime.h>

#define Bsz 2048
#define Ncm 128
#define Dh  512

// 8MB scratch for cw = content @ cow  (rows interleaved: m = 2*b + k)
__device__ float g_cw[2 * Bsz * Dh];

__device__ __forceinline__ float fast_tanh(float x) {
    float e = __expf(-2.0f * fabsf(x));
    float r = __fdividef(1.0f - e, 1.0f + e);
    return copysignf(r, x);
}

// ---------------------------------------------------------------------------
// Kernel 1: cw[m, e] = sum_d A[m, d] * cow[d, e]
//   A row m comes from text (m even) or img (m odd), sample b = m>>1.
//   M = 2*Bsz = 4096, N = K = 512.  BM=128, BN=64, BK=16, 256 threads, 8x4/thr.
// ---------------------------------------------------------------------------
#define BM 128
#define BN 64
#define BK 16

__global__ __launch_bounds__(256) void gemm_cw_kernel(
    const float* __restrict__ text,
    const float* __restrict__ img,
    const float* __restrict__ cow)
{
    __shared__ float As[BK][BM + 4];
    __shared__ float Bs[BK][BN];

    const int tid = threadIdx.x;
    const int m0 = blockIdx.y * BM;
    const int n0 = blockIdx.x * BN;
    const int ty = tid >> 4;   // 0..15 -> row group of 8
    const int tx = tid & 15;   // 0..15 -> col group of 4

    float acc[8][4];
#pragma unroll
    for (int i = 0; i < 8; i++)
#pragma unroll
        for (int j = 0; j < 4; j++) acc[i][j] = 0.0f;

    for (int kk = 0; kk < Dh; kk += BK) {
        // Load A tile: 128 rows x 16 cols = 512 float4, 2 per thread.
#pragma unroll
        for (int q = 0; q < 2; q++) {
            int li  = tid * 2 + q;
            int row = li >> 2;
            int c4  = li & 3;
            int m   = m0 + row;
            const float* src = (m & 1) ? img : text;
            float4 v = *(const float4*)(src + (size_t)(m >> 1) * Dh + kk + c4 * 4);
            As[c4 * 4 + 0][row] = v.x;
            As[c4 * 4 + 1][row] = v.y;
            As[c4 * 4 + 2][row] = v.z;
            As[c4 * 4 + 3][row] = v.w;
        }
        // Load B tile: 16 rows x 64 cols = 256 float4, 1 per thread.
        {
            int row = tid >> 4;
            int c4  = tid & 15;
            float4 v = *(const float4*)(cow + (size_t)(kk + row) * Dh + n0 + c4 * 4);
            *(float4*)&Bs[row][c4 * 4] = v;
        }
        __syncthreads();

#pragma unroll
        for (int k = 0; k < BK; k++) {
            float a[8], bv[4];
#pragma unroll
            for (int i = 0; i < 8; i++) a[i] = As[k][ty * 8 + i];
#pragma unroll
            for (int j = 0; j < 4; j++) bv[j] = Bs[k][tx * 4 + j];
#pragma unroll
            for (int i = 0; i < 8; i++)
#pragma unroll
                for (int j = 0; j < 4; j++) acc[i][j] += a[i] * bv[j];
        }
        __syncthreads();
    }

#pragma unroll
    for (int i = 0; i < 8; i++) {
        size_t row = (size_t)(m0 + ty * 8 + i) * Dh + n0 + tx * 4;
#pragma unroll
        for (int j = 0; j < 4; j++) g_cw[row + j] = acc[i][j];
    }
}

// ---------------------------------------------------------------------------
// Kernel 2: fused co-attention. One CTA per sample, 8 warps, warp-per-comment.
// Lane l owns d in [16l, 16l+16). Single pass over valid comment rows with
// online (max-free) softmax accumulation.
// ---------------------------------------------------------------------------
__global__ __launch_bounds__(256, 1) void fused_coattn_kernel(
    const float* __restrict__ text,
    const float* __restrict__ img,
    const float* __restrict__ comment,
    const int*   __restrict__ comment_num,
    const float* __restrict__ W_ca,
    const float* __restrict__ b_ca,
    const float* __restrict__ W_co,
    const float* __restrict__ b_co,
    float* __restrict__ out)
{
    const int b    = blockIdx.x;
    const int tid  = threadIdx.x;
    const int lane = tid & 31;
    const int warp = tid >> 5;
    const int base = lane << 4;   // 16 floats per lane

    int cn = comment_num[b];
    if (cn > Ncm) cn = Ncm;
    if (cn < 0)   cn = 0;

    const float* tp  = text + (size_t)b * Dh;
    const float* ip  = img  + (size_t)b * Dh;
    const float* w0p = g_cw + (size_t)(2 * b) * Dh;
    const float* w1p = w0p + Dh;

    float c0[16], c1[16], w0r[16], w1r[16], wco[16];
#pragma unroll
    for (int q = 0; q < 4; q++) {
        ((float4*)c0)[q]  = ((const float4*)(tp  + base))[q];
        ((float4*)c1)[q]  = ((const float4*)(ip  + base))[q];
        ((float4*)w0r)[q] = ((const float4*)(w0p + base))[q];
        ((float4*)w1r)[q] = ((const float4*)(w1p + base))[q];
        ((float4*)wco)[q] = ((const float4*)(W_co + base))[q];
    }

    float caA[16], caB[16], accv[16];
#pragma unroll
    for (int i = 0; i < 16; i++) { caA[i] = 0.f; caB[i] = 0.f; accv[i] = 0.f; }
    float ssum = 0.0f;
    const float bco = b_co[0];

    for (int n = warp; n < cn; n += 8) {
        const float4* zp = (const float4*)(comment + ((size_t)b * Ncm + n) * Dh + base);
        float z[16];
#pragma unroll
        for (int q = 0; q < 4; q++) ((float4*)z)[q] = zp[q];

        // co_w[k,n] = tanh(cw[k] . z[n])
        float d0 = 0.f, d1 = 0.f;
#pragma unroll
        for (int i = 0; i < 16; i++) { d0 += w0r[i] * z[i]; d1 += w1r[i] * z[i]; }
#pragma unroll
        for (int o = 16; o > 0; o >>= 1) {
            d0 += __shfl_xor_sync(0xffffffffu, d0, o);
            d1 += __shfl_xor_sync(0xffffffffu, d1, o);
        }
        float co0 = fast_tanh(d0);
        float co1 = fast_tanh(d1);

        // caccum[k] += co_w[k,n] * z[n]; comment logit partial
        float pd = 0.f;
#pragma unroll
        for (int i = 0; i < 16; i++) {
            caA[i] += co0 * z[i];
            caB[i] += co1 * z[i];
            float t = fast_tanh(z[i] + co0 * c0[i] + co1 * c1[i]);
            pd += t * wco[i];
        }
#pragma unroll
        for (int o = 16; o > 0; o >>= 1)
            pd += __shfl_xor_sync(0xffffffffu, pd, o);

        // |logit| <= ||W_co||_1 ~ 18, so raw exp is safe in fp32.
        float e = __expf(pd + bco);
        ssum += e;
#pragma unroll
        for (int i = 0; i < 16; i++) accv[i] += e * z[i];
    }

    // ---- cross-warp reductions via smem ----
    __shared__ float sbuf[8 * Dh];           // 16 KB staging
    __shared__ float rA[Dh], rB[Dh], rC[Dh]; // 6 KB results
    __shared__ float swr[8];
    __shared__ float pr[16];
    __shared__ float sscal[3];

    if (lane == 0) swr[warp] = ssum;

#pragma unroll
    for (int i = 0; i < 16; i++) sbuf[warp * Dh + base + i] = caA[i];
    __syncthreads();
    for (int d = tid; d < Dh; d += 256) {
        float s = 0.f;
#pragma unroll
        for (int w = 0; w < 8; w++) s += sbuf[w * Dh + d];
        rA[d] = s;
    }
    __syncthreads();
#pragma unroll
    for (int i = 0; i < 16; i++) sbuf[warp * Dh + base + i] = caB[i];
    __syncthreads();
    for (int d = tid; d < Dh; d += 256) {
        float s = 0.f;
#pragma unroll
        for (int w = 0; w < 8; w++) s += sbuf[w * Dh + d];
        rB[d] = s;
    }
    __syncthreads();
#pragma unroll
    for (int i = 0; i < 16; i++) sbuf[warp * Dh + base + i] = accv[i];
    __syncthreads();
    for (int d = tid; d < Dh; d += 256) {
        float s = 0.f;
#pragma unroll
        for (int w = 0; w < 8; w++) s += sbuf[w * Dh + d];
        rC[d] = s;
    }
    __syncthreads();

    // ---- content attention logits ----
    float p0 = 0.f, p1 = 0.f;
    for (int d = tid; d < Dh; d += 256) {
        float wa = W_ca[d];
        p0 += fast_tanh(tp[d] + rA[d]) * wa;
        p1 += fast_tanh(ip[d] + rB[d]) * wa;
    }
#pragma unroll
    for (int o = 16; o > 0; o >>= 1) {
        p0 += __shfl_xor_sync(0xffffffffu, p0, o);
        p1 += __shfl_xor_sync(0xffffffffu, p1, o);
    }
    if (lane == 0) { pr[warp] = p0; pr[8 + warp] = p1; }
    __syncthreads();

    if (tid == 0) {
        float bca = b_ca[0];
        float l0 = bca, l1 = bca;
#pragma unroll
        for (int w = 0; w < 8; w++) { l0 += pr[w]; l1 += pr[8 + w]; }
        float mx = fmaxf(l0, l1);
        float e0 = __expf(l0 - mx), e1 = __expf(l1 - mx);
        float inv = __fdividef(1.0f, e0 + e1);
        float st = 0.f;
#pragma unroll
        for (int w = 0; w < 8; w++) st += swr[w];
        sscal[0] = e0 * inv;
        sscal[1] = e1 * inv;
        sscal[2] = __fdividef(1.0f, st);
    }
    __syncthreads();

    const float cwt0 = sscal[0], cwt1 = sscal[1], invs = sscal[2];
    for (int d = tid; d < Dh; d += 256) {
        out[(size_t)b * Dh + d]              = tp[d] * cwt0 + ip[d] * cwt1;
        out[(size_t)(Bsz + b) * Dh + d]      = rC[d] * invs;
    }
    if (tid == 0) {
        out[(size_t)2 * Bsz * Dh + 2 * b]     = cwt0;
        out[(size_t)2 * Bsz * Dh + 2 * b + 1] = cwt1;
    }
}

// ---------------------------------------------------------------------------
extern "C" void kernel_launch(void* const* d_in, const int* in_sizes, int n_in,
                              void* d_out, int out_size)
{
    const float* text    = (const float*)d_in[0];
    const float* img     = (const float*)d_in[1];
    const float* comment = (const float*)d_in[2];
    const int*   cnum    = (const int*)d_in[3];
    const float* cow     = (const float*)d_in[4];
    const float* W_ca    = (const float*)d_in[5];
    const float* b_ca    = (const float*)d_in[6];
    const float* W_co    = (const float*)d_in[7];
    const float* b_co    = (const float*)d_in[8];
    float* out = (float*)d_out;

    dim3 ggrid(Dh / BN, (2 * Bsz) / BM);   // (8, 32)
    gemm_cw_kernel<<<ggrid, 256>>>(text, img, cow);
    fused_coattn_kernel<<<Bsz, 256>>>(text, img, comment, cnum,
                                      W_ca, b_ca, W_co, b_co, out);
}

// round 6
// speedup vs baseline: 1.1944x; 1.1944x over previous
#include <cuda_runtime.h>

#define Bsz 2048
#define Ncm 128
#define Dh  512

// 8MB scratch for cw = content @ cow  (rows interleaved: m = 2*b + k)
__device__ float g_cw[2 * Bsz * Dh];

__device__ __forceinline__ float fast_tanh(float x) {
    float y;
    asm("tanh.approx.f32 %0, %1;" : "=f"(y) : "f"(x));
    return y;
}

// ---------------------------------------------------------------------------
// Kernel 1: cw[m, e] = sum_d A[m, d] * cow[d, e]
//   A row m comes from text (m even) or img (m odd), sample b = m>>1.
//   M = 2*Bsz = 4096, N = K = 512.  BM=128, BN=64, BK=16, 256 threads, 8x4/thr.
// ---------------------------------------------------------------------------
#define BM 128
#define BN 64
#define BK 16

__global__ __launch_bounds__(256) void gemm_cw_kernel(
    const float* __restrict__ text,
    const float* __restrict__ img,
    const float* __restrict__ cow)
{
    __shared__ float As[BK][BM + 4];
    __shared__ float Bs[BK][BN];

    const int tid = threadIdx.x;
    const int m0 = blockIdx.y * BM;
    const int n0 = blockIdx.x * BN;
    const int ty = tid >> 4;   // 0..15 -> row group of 8
    const int tx = tid & 15;   // 0..15 -> col group of 4

    float acc[8][4];
#pragma unroll
    for (int i = 0; i < 8; i++)
#pragma unroll
        for (int j = 0; j < 4; j++) acc[i][j] = 0.0f;

    for (int kk = 0; kk < Dh; kk += BK) {
#pragma unroll
        for (int q = 0; q < 2; q++) {
            int li  = tid * 2 + q;
            int row = li >> 2;
            int c4  = li & 3;
            int m   = m0 + row;
            const float* src = (m & 1) ? img : text;
            float4 v = *(const float4*)(src + (size_t)(m >> 1) * Dh + kk + c4 * 4);
            As[c4 * 4 + 0][row] = v.x;
            As[c4 * 4 + 1][row] = v.y;
            As[c4 * 4 + 2][row] = v.z;
            As[c4 * 4 + 3][row] = v.w;
        }
        {
            int row = tid >> 4;
            int c4  = tid & 15;
            float4 v = *(const float4*)(cow + (size_t)(kk + row) * Dh + n0 + c4 * 4);
            *(float4*)&Bs[row][c4 * 4] = v;
        }
        __syncthreads();

#pragma unroll
        for (int k = 0; k < BK; k++) {
            float a[8], bv[4];
#pragma unroll
            for (int i = 0; i < 8; i++) a[i] = As[k][ty * 8 + i];
#pragma unroll
            for (int j = 0; j < 4; j++) bv[j] = Bs[k][tx * 4 + j];
#pragma unroll
            for (int i = 0; i < 8; i++)
#pragma unroll
                for (int j = 0; j < 4; j++) acc[i][j] += a[i] * bv[j];
        }
        __syncthreads();
    }

#pragma unroll
    for (int i = 0; i < 8; i++) {
        size_t row = (size_t)(m0 + ty * 8 + i) * Dh + n0 + tx * 4;
#pragma unroll
        for (int j = 0; j < 4; j++) g_cw[row + j] = acc[i][j];
    }
}

// ---------------------------------------------------------------------------
// Kernel 2: fused co-attention. One CTA per sample, 8 warps.
// 2-way ILP: each warp processes comments (n, n+8) per iteration with two
// interleaved independent dependency chains. Lane l owns d in [16l, 16l+16).
// ---------------------------------------------------------------------------
__global__ __launch_bounds__(256, 1) void fused_coattn_kernel(
    const float* __restrict__ text,
    const float* __restrict__ img,
    const float* __restrict__ comment,
    const int*   __restrict__ comment_num,
    const float* __restrict__ W_ca,
    const float* __restrict__ b_ca,
    const float* __restrict__ W_co,
    const float* __restrict__ b_co,
    float* __restrict__ out)
{
    const int b    = blockIdx.x;
    const int tid  = threadIdx.x;
    const int lane = tid & 31;
    const int warp = tid >> 5;
    const int base = lane << 4;   // 16 floats per lane

    int cn = comment_num[b];
    if (cn > Ncm) cn = Ncm;
    if (cn < 0)   cn = 0;

    const float* tp  = text + (size_t)b * Dh;
    const float* ip  = img  + (size_t)b * Dh;
    const float* w0p = g_cw + (size_t)(2 * b) * Dh;
    const float* w1p = w0p + Dh;

    float c0[16], c1[16], w0r[16], w1r[16], wco[16];
#pragma unroll
    for (int q = 0; q < 4; q++) {
        ((float4*)c0)[q]  = ((const float4*)(tp  + base))[q];
        ((float4*)c1)[q]  = ((const float4*)(ip  + base))[q];
        ((float4*)w0r)[q] = ((const float4*)(w0p + base))[q];
        ((float4*)w1r)[q] = ((const float4*)(w1p + base))[q];
        ((float4*)wco)[q] = ((const float4*)(W_co + base))[q];
    }

    float caA[16], caB[16], accv[16];
#pragma unroll
    for (int i = 0; i < 16; i++) { caA[i] = 0.f; caB[i] = 0.f; accv[i] = 0.f; }
    float ssum = 0.0f;
    const float bco = b_co[0];

    const float* cbase = comment + (size_t)b * Ncm * Dh + base;

    for (int n = warp; n < cn; n += 16) {
        const int nb = n + 8;
        const bool hb = nb < cn;
        const float fb = hb ? 1.0f : 0.0f;

        float za[16], zb[16];
        const float4* zpa = (const float4*)(cbase + (size_t)n * Dh);
        const float4* zpb = (const float4*)(cbase + (size_t)(hb ? nb : n) * Dh);
#pragma unroll
        for (int q = 0; q < 4; q++) { ((float4*)za)[q] = zpa[q]; ((float4*)zb)[q] = zpb[q]; }

        // co_w[k,n] = tanh(cw[k] . z[n]) — two comments interleaved
        float d0a = 0.f, d1a = 0.f, d0b = 0.f, d1b = 0.f;
#pragma unroll
        for (int i = 0; i < 16; i++) {
            d0a += w0r[i] * za[i]; d1a += w1r[i] * za[i];
            d0b += w0r[i] * zb[i]; d1b += w1r[i] * zb[i];
        }
#pragma unroll
        for (int o = 16; o > 0; o >>= 1) {
            d0a += __shfl_xor_sync(0xffffffffu, d0a, o);
            d1a += __shfl_xor_sync(0xffffffffu, d1a, o);
            d0b += __shfl_xor_sync(0xffffffffu, d0b, o);
            d1b += __shfl_xor_sync(0xffffffffu, d1b, o);
        }
        float co0a = fast_tanh(d0a);
        float co1a = fast_tanh(d1a);
        float co0b = fast_tanh(d0b) * fb;
        float co1b = fast_tanh(d1b) * fb;

        // accumulate co_w*z; comment logit partials
        float pda = 0.f, pdb = 0.f;
#pragma unroll
        for (int i = 0; i < 16; i++) {
            caA[i] += co0a * za[i] + co0b * zb[i];
            caB[i] += co1a * za[i] + co1b * zb[i];
            float ta = fast_tanh(za[i] + co0a * c0[i] + co1a * c1[i]);
            float tb = fast_tanh(zb[i] + co0b * c0[i] + co1b * c1[i]);
            pda += ta * wco[i];
            pdb += tb * wco[i];
        }
#pragma unroll
        for (int o = 16; o > 0; o >>= 1) {
            pda += __shfl_xor_sync(0xffffffffu, pda, o);
            pdb += __shfl_xor_sync(0xffffffffu, pdb, o);
        }

        // |logit| <= ||W_co||_1 ~ 18, raw exp safe in fp32.
        float ea = __expf(pda + bco);
        float eb = __expf(pdb + bco) * fb;
        ssum += ea + eb;
#pragma unroll
        for (int i = 0; i < 16; i++) accv[i] += ea * za[i] + eb * zb[i];
    }

    // ---- cross-warp reductions via smem ----
    __shared__ float sbuf[8 * Dh];           // 16 KB staging
    __shared__ float rA[Dh], rB[Dh], rC[Dh]; // 6 KB results
    __shared__ float swr[8];
    __shared__ float pr[16];
    __shared__ float sscal[3];

    if (lane == 0) swr[warp] = ssum;

#pragma unroll
    for (int i = 0; i < 16; i++) sbuf[warp * Dh + base + i] = caA[i];
    __syncthreads();
    for (int d = tid; d < Dh; d += 256) {
        float s = 0.f;
#pragma unroll
        for (int w = 0; w < 8; w++) s += sbuf[w * Dh + d];
        rA[d] = s;
    }
    __syncthreads();
#pragma unroll
    for (int i = 0; i < 16; i++) sbuf[warp * Dh + base + i] = caB[i];
    __syncthreads();
    for (int d = tid; d < Dh; d += 256) {
        float s = 0.f;
#pragma unroll
        for (int w = 0; w < 8; w++) s += sbuf[w * Dh + d];
        rB[d] = s;
    }
    __syncthreads();
#pragma unroll
    for (int i = 0; i < 16; i++) sbuf[warp * Dh + base + i] = accv[i];
    __syncthreads();
    for (int d = tid; d < Dh; d += 256) {
        float s = 0.f;
#pragma unroll
        for (int w = 0; w < 8; w++) s += sbuf[w * Dh + d];
        rC[d] = s;
    }
    __syncthreads();

    // ---- content attention logits ----
    float p0 = 0.f, p1 = 0.f;
    for (int d = tid; d < Dh; d += 256) {
        float wa = W_ca[d];
        p0 += fast_tanh(tp[d] + rA[d]) * wa;
        p1 += fast_tanh(ip[d] + rB[d]) * wa;
    }
#pragma unroll
    for (int o = 16; o > 0; o >>= 1) {
        p0 += __shfl_xor_sync(0xffffffffu, p0, o);
        p1 += __shfl_xor_sync(0xffffffffu, p1, o);
    }
    if (lane == 0) { pr[warp] = p0; pr[8 + warp] = p1; }
    __syncthreads();

    if (tid == 0) {
        float bca = b_ca[0];
        float l0 = bca, l1 = bca;
#pragma unroll
        for (int w = 0; w < 8; w++) { l0 += pr[w]; l1 += pr[8 + w]; }
        float mx = fmaxf(l0, l1);
        float e0 = __expf(l0 - mx), e1 = __expf(l1 - mx);
        float inv = __fdividef(1.0f, e0 + e1);
        float st = 0.f;
#pragma unroll
        for (int w = 0; w < 8; w++) st += swr[w];
        sscal[0] = e0 * inv;
        sscal[1] = e1 * inv;
        sscal[2] = __fdividef(1.0f, st);
    }
    __syncthreads();

    const float cwt0 = sscal[0], cwt1 = sscal[1], invs = sscal[2];
    for (int d = tid; d < Dh; d += 256) {
        out[(size_t)b * Dh + d]              = tp[d] * cwt0 + ip[d] * cwt1;
        out[(size_t)(Bsz + b) * Dh + d]      = rC[d] * invs;
    }
    if (tid == 0) {
        out[(size_t)2 * Bsz * Dh + 2 * b]     = cwt0;
        out[(size_t)2 * Bsz * Dh + 2 * b + 1] = cwt1;
    }
}

// ---------------------------------------------------------------------------
extern "C" void kernel_launch(void* const* d_in, const int* in_sizes, int n_in,
                              void* d_out, int out_size)
{
    const float* text    = (const float*)d_in[0];
    const float* img     = (const float*)d_in[1];
    const float* comment = (const float*)d_in[2];
    const int*   cnum    = (const int*)d_in[3];
    const float* cow     = (const float*)d_in[4];
    const float* W_ca    = (const float*)d_in[5];
    const float* b_ca    = (const float*)d_in[6];
    const float* W_co    = (const float*)d_in[7];
    const float* b_co    = (const float*)d_in[8];
    float* out = (float*)d_out;

    dim3 ggrid(Dh / BN, (2 * Bsz) / BM);   // (8, 32)
    gemm_cw_kernel<<<ggrid, 256>>>(text, img, cow);
    fused_coattn_kernel<<<Bsz, 256>>>(text, img, comment, cnum,
                                      W_ca, b_ca, W_co, b_co, out);
}

// round 7
// speedup vs baseline: 1.2394x; 1.0376x over previous
#include <cuda_runtime.h>

#define Bsz 2048
#define Ncm 128
#define Dh  512

// 8MB scratch for cw = content @ cow  (rows interleaved: m = 2*b + k)
__device__ float g_cw[2 * Bsz * Dh];

__device__ __forceinline__ float fast_tanh(float x) {
    float y;
    asm("tanh.approx.f32 %0, %1;" : "=f"(y) : "f"(x));
    return y;
}

// ---------------------------------------------------------------------------
// Kernel 1: cw[m, e] = sum_d A[m, d] * cow[d, e]
//   M = 2*Bsz = 4096, N = K = 512.  BM=128, BN=64, BK=16, 256 threads, 8x4/thr.
// ---------------------------------------------------------------------------
#define BM 128
#define BN 64
#define BK 16

__global__ __launch_bounds__(256) void gemm_cw_kernel(
    const float* __restrict__ text,
    const float* __restrict__ img,
    const float* __restrict__ cow)
{
    __shared__ float As[BK][BM + 4];
    __shared__ float Bs[BK][BN];

    const int tid = threadIdx.x;
    const int m0 = blockIdx.y * BM;
    const int n0 = blockIdx.x * BN;
    const int ty = tid >> 4;
    const int tx = tid & 15;

    float acc[8][4];
#pragma unroll
    for (int i = 0; i < 8; i++)
#pragma unroll
        for (int j = 0; j < 4; j++) acc[i][j] = 0.0f;

    for (int kk = 0; kk < Dh; kk += BK) {
#pragma unroll
        for (int q = 0; q < 2; q++) {
            int li  = tid * 2 + q;
            int row = li >> 2;
            int c4  = li & 3;
            int m   = m0 + row;
            const float* src = (m & 1) ? img : text;
            float4 v = *(const float4*)(src + (size_t)(m >> 1) * Dh + kk + c4 * 4);
            As[c4 * 4 + 0][row] = v.x;
            As[c4 * 4 + 1][row] = v.y;
            As[c4 * 4 + 2][row] = v.z;
            As[c4 * 4 + 3][row] = v.w;
        }
        {
            int row = tid >> 4;
            int c4  = tid & 15;
            float4 v = *(const float4*)(cow + (size_t)(kk + row) * Dh + n0 + c4 * 4);
            *(float4*)&Bs[row][c4 * 4] = v;
        }
        __syncthreads();

#pragma unroll
        for (int k = 0; k < BK; k++) {
            float a[8], bv[4];
#pragma unroll
            for (int i = 0; i < 8; i++) a[i] = As[k][ty * 8 + i];
#pragma unroll
            for (int j = 0; j < 4; j++) bv[j] = Bs[k][tx * 4 + j];
#pragma unroll
            for (int i = 0; i < 8; i++)
#pragma unroll
                for (int j = 0; j < 4; j++) acc[i][j] += a[i] * bv[j];
        }
        __syncthreads();
    }

#pragma unroll
    for (int i = 0; i < 8; i++) {
        size_t row = (size_t)(m0 + ty * 8 + i) * Dh + n0 + tx * 4;
#pragma unroll
        for (int j = 0; j < 4; j++) g_cw[row + j] = acc[i][j];
    }
}

// ---------------------------------------------------------------------------
// Kernel 2: fused co-attention. One CTA per sample, 8 warps.
// 2-way ILP (comments n, n+8 per compute step) + double-buffered prefetch of
// the next iteration's z rows so DRAM latency overlaps compute.
// c0/c1/W_co live in shared memory to keep registers under control.
// ---------------------------------------------------------------------------
__global__ __launch_bounds__(256, 1) void fused_coattn_kernel(
    const float* __restrict__ text,
    const float* __restrict__ img,
    const float* __restrict__ comment,
    const int*   __restrict__ comment_num,
    const float* __restrict__ W_ca,
    const float* __restrict__ b_ca,
    const float* __restrict__ W_co,
    const float* __restrict__ b_co,
    float* __restrict__ out)
{
    const int b    = blockIdx.x;
    const int tid  = threadIdx.x;
    const int lane = tid & 31;
    const int warp = tid >> 5;
    const int base = lane << 4;   // 16 floats per lane

    __shared__ float sc0[Dh], sc1[Dh], swco[Dh];
    __shared__ float sbuf[8 * Dh];           // 16 KB staging
    __shared__ float rA[Dh], rB[Dh], rC[Dh];
    __shared__ float swr[8];
    __shared__ float pr[16];
    __shared__ float sscal[3];

    int cn = comment_num[b];
    if (cn > Ncm) cn = Ncm;
    if (cn < 1)   cn = 1;

    const float* tp  = text + (size_t)b * Dh;
    const float* ip  = img  + (size_t)b * Dh;
    const float* w0p = g_cw + (size_t)(2 * b) * Dh;
    const float* w1p = w0p + Dh;

    // per-lane register state
    float w0r[16], w1r[16];
#pragma unroll
    for (int q = 0; q < 4; q++) {
        ((float4*)w0r)[q] = ((const float4*)(w0p + base))[q];
        ((float4*)w1r)[q] = ((const float4*)(w1p + base))[q];
    }
    // per-CTA shared state
    for (int d = tid * 4; d < Dh; d += 256 * 4) {
        *(float4*)&sc0[d]  = *(const float4*)(tp + d);
        *(float4*)&sc1[d]  = *(const float4*)(ip + d);
        *(float4*)&swco[d] = *(const float4*)(W_co + d);
    }
    __syncthreads();

    float caA[16], caB[16], accv[16];
#pragma unroll
    for (int i = 0; i < 16; i++) { caA[i] = 0.f; caB[i] = 0.f; accv[i] = 0.f; }
    float ssum = 0.0f;
    const float bco = b_co[0];

    const float* cbase = comment + (size_t)b * Ncm * Dh + base;

    float z0[32], z1[32];

    auto loadpair = [&](float (&z)[32], int n) {
        int nb = n + 8; if (nb >= cn) nb = n;
        const float4* pa = (const float4*)(cbase + (size_t)n  * Dh);
        const float4* pb = (const float4*)(cbase + (size_t)nb * Dh);
#pragma unroll
        for (int q = 0; q < 4; q++) {
            ((float4*)z)[q]        = pa[q];
            ((float4*)(z + 16))[q] = pb[q];
        }
    };

    auto compute = [&](const float (&z)[32], int n) {
        const float fb = (n + 8 < cn) ? 1.0f : 0.0f;

        float d0a = 0.f, d1a = 0.f, d0b = 0.f, d1b = 0.f;
#pragma unroll
        for (int i = 0; i < 16; i++) {
            d0a += w0r[i] * z[i];      d1a += w1r[i] * z[i];
            d0b += w0r[i] * z[16 + i]; d1b += w1r[i] * z[16 + i];
        }
#pragma unroll
        for (int o = 16; o > 0; o >>= 1) {
            d0a += __shfl_xor_sync(0xffffffffu, d0a, o);
            d1a += __shfl_xor_sync(0xffffffffu, d1a, o);
            d0b += __shfl_xor_sync(0xffffffffu, d0b, o);
            d1b += __shfl_xor_sync(0xffffffffu, d1b, o);
        }
        float co0a = fast_tanh(d0a);
        float co1a = fast_tanh(d1a);
        float co0b = fast_tanh(d0b) * fb;
        float co1b = fast_tanh(d1b) * fb;

        float pda = 0.f, pdb = 0.f;
#pragma unroll
        for (int q = 0; q < 4; q++) {
            float4 c0v = *(const float4*)&sc0[base + q * 4];
            float4 c1v = *(const float4*)&sc1[base + q * 4];
            float4 wv  = *(const float4*)&swco[base + q * 4];
            const float c0j[4] = {c0v.x, c0v.y, c0v.z, c0v.w};
            const float c1j[4] = {c1v.x, c1v.y, c1v.z, c1v.w};
            const float wj[4]  = {wv.x,  wv.y,  wv.z,  wv.w};
#pragma unroll
            for (int j = 0; j < 4; j++) {
                int i = q * 4 + j;
                caA[i] += co0a * z[i] + co0b * z[16 + i];
                caB[i] += co1a * z[i] + co1b * z[16 + i];
                float ta = fast_tanh(z[i]      + co0a * c0j[j] + co1a * c1j[j]);
                float tb = fast_tanh(z[16 + i] + co0b * c0j[j] + co1b * c1j[j]);
                pda += ta * wj[j];
                pdb += tb * wj[j];
            }
        }
#pragma unroll
        for (int o = 16; o > 0; o >>= 1) {
            pda += __shfl_xor_sync(0xffffffffu, pda, o);
            pdb += __shfl_xor_sync(0xffffffffu, pdb, o);
        }

        float ea = __expf(pda + bco);
        float eb = __expf(pdb + bco) * fb;
        ssum += ea + eb;
#pragma unroll
        for (int i = 0; i < 16; i++) accv[i] += ea * z[i] + eb * z[16 + i];
    };

    // software-pipelined main loop (double buffer, unrolled x2 to avoid copies)
    int n = warp;
    if (n < cn) {
        loadpair(z0, n);
        while (true) {
            int n2 = n + 16;
            if (n2 < cn) loadpair(z1, n2);
            compute(z0, n);
            if (n2 >= cn) break;
            int n3 = n2 + 16;
            if (n3 < cn) loadpair(z0, n3);
            compute(z1, n2);
            if (n3 >= cn) break;
            n = n3;
        }
    }

    // ---- cross-warp reductions via smem (3 passes over one staging buffer) ----
    if (lane == 0) swr[warp] = ssum;

#pragma unroll
    for (int i = 0; i < 16; i++) sbuf[warp * Dh + base + i] = caA[i];
    __syncthreads();
    for (int d = tid; d < Dh; d += 256) {
        float s = 0.f;
#pragma unroll
        for (int w = 0; w < 8; w++) s += sbuf[w * Dh + d];
        rA[d] = s;
    }
    __syncthreads();
#pragma unroll
    for (int i = 0; i < 16; i++) sbuf[warp * Dh + base + i] = caB[i];
    __syncthreads();
    for (int d = tid; d < Dh; d += 256) {
        float s = 0.f;
#pragma unroll
        for (int w = 0; w < 8; w++) s += sbuf[w * Dh + d];
        rB[d] = s;
    }
    __syncthreads();
#pragma unroll
    for (int i = 0; i < 16; i++) sbuf[warp * Dh + base + i] = accv[i];
    __syncthreads();
    for (int d = tid; d < Dh; d += 256) {
        float s = 0.f;
#pragma unroll
        for (int w = 0; w < 8; w++) s += sbuf[w * Dh + d];
        rC[d] = s;
    }
    __syncthreads();

    // ---- content attention logits ----
    float p0 = 0.f, p1 = 0.f;
    for (int d = tid; d < Dh; d += 256) {
        float wa = W_ca[d];
        p0 += fast_tanh(sc0[d] + rA[d]) * wa;
        p1 += fast_tanh(sc1[d] + rB[d]) * wa;
    }
#pragma unroll
    for (int o = 16; o > 0; o >>= 1) {
        p0 += __shfl_xor_sync(0xffffffffu, p0, o);
        p1 += __shfl_xor_sync(0xffffffffu, p1, o);
    }
    if (lane == 0) { pr[warp] = p0; pr[8 + warp] = p1; }
    __syncthreads();

    if (tid == 0) {
        float bca = b_ca[0];
        float l0 = bca, l1 = bca;
#pragma unroll
        for (int w = 0; w < 8; w++) { l0 += pr[w]; l1 += pr[8 + w]; }
        float mx = fmaxf(l0, l1);
        float e0 = __expf(l0 - mx), e1 = __expf(l1 - mx);
        float inv = __fdividef(1.0f, e0 + e1);
        float st = 0.f;
#pragma unroll
        for (int w = 0; w < 8; w++) st += swr[w];
        sscal[0] = e0 * inv;
        sscal[1] = e1 * inv;
        sscal[2] = __fdividef(1.0f, st);
    }
    __syncthreads();

    const float cwt0 = sscal[0], cwt1 = sscal[1], invs = sscal[2];
    for (int d = tid; d < Dh; d += 256) {
        out[(size_t)b * Dh + d]         = sc0[d] * cwt0 + sc1[d] * cwt1;
        out[(size_t)(Bsz + b) * Dh + d] = rC[d] * invs;
    }
    if (tid == 0) {
        out[(size_t)2 * Bsz * Dh + 2 * b]     = cwt0;
        out[(size_t)2 * Bsz * Dh + 2 * b + 1] = cwt1;
    }
}

// ---------------------------------------------------------------------------
extern "C" void kernel_launch(void* const* d_in, const int* in_sizes, int n_in,
                              void* d_out, int out_size)
{
    const float* text    = (const float*)d_in[0];
    const float* img     = (const float*)d_in[1];
    const float* comment = (const float*)d_in[2];
    const int*   cnum    = (const int*)d_in[3];
    const float* cow     = (const float*)d_in[4];
    const float* W_ca    = (const float*)d_in[5];
    const float* b_ca    = (const float*)d_in[6];
    const float* W_co    = (const float*)d_in[7];
    const float* b_co    = (const float*)d_in[8];
    float* out = (float*)d_out;

    dim3 ggrid(Dh / BN, (2 * Bsz) / BM);   // (8, 32)
    gemm_cw_kernel<<<ggrid, 256>>>(text, img, cow);
    fused_coattn_kernel<<<Bsz, 256>>>(text, img, comment, cnum,
                                      W_ca, b_ca, W_co, b_co, out);
}

// round 8
// speedup vs baseline: 1.6345x; 1.3188x over previous
#include <cuda_runtime.h>

#define Bsz 2048
#define Ncm 128
#define Dh  512

// 8MB scratch for cw = content @ cow  (rows interleaved: m = 2*b + k)
__device__ float g_cw[2 * Bsz * Dh];

__device__ __forceinline__ float fast_tanh(float x) {
    float y;
    asm("tanh.approx.f32 %0, %1;" : "=f"(y) : "f"(x));
    return y;
}

__device__ __forceinline__ unsigned long long fma2(unsigned long long a,
                                                   unsigned long long b,
                                                   unsigned long long c) {
    unsigned long long d;
    asm("fma.rn.f32x2 %0, %1, %2, %3;" : "=l"(d) : "l"(a), "l"(b), "l"(c));
    return d;
}

__device__ __forceinline__ unsigned long long pack2(float v) {
    unsigned long long d;
    asm("mov.b64 %0, {%1, %1};" : "=l"(d) : "f"(v));
    return d;
}

// ---------------------------------------------------------------------------
// Kernel 1: cw[m, e] = sum_d A[m, d] * cow[d, e]   (FFMA2 / f32x2 mainloop)
//   M = 2*Bsz = 4096, N = K = 512.  BM=128, BN=64, BK=16, 256 threads.
//   Each thread: 8 rows (as 4 f32x2 pairs) x 4 cols.
// ---------------------------------------------------------------------------
#define BM 128
#define BN 64
#define BK 16

__global__ __launch_bounds__(256) void gemm_cw_kernel(
    const float* __restrict__ text,
    const float* __restrict__ img,
    const float* __restrict__ cow)
{
    __shared__ float As[BK][BM + 4];
    __shared__ float Bs[BK][BN];

    const int tid = threadIdx.x;
    const int m0 = blockIdx.y * BM;
    const int n0 = blockIdx.x * BN;
    const int ty = tid >> 4;   // 0..15 -> row group of 8
    const int tx = tid & 15;   // 0..15 -> col group of 4

    unsigned long long acc2[4][4];   // [row-pair][col] packed f32x2
#pragma unroll
    for (int i = 0; i < 4; i++)
#pragma unroll
        for (int j = 0; j < 4; j++) acc2[i][j] = 0ull;

    for (int kk = 0; kk < Dh; kk += BK) {
#pragma unroll
        for (int q = 0; q < 2; q++) {
            int li  = tid * 2 + q;
            int row = li >> 2;
            int c4  = li & 3;
            int m   = m0 + row;
            const float* src = (m & 1) ? img : text;
            float4 v = *(const float4*)(src + (size_t)(m >> 1) * Dh + kk + c4 * 4);
            As[c4 * 4 + 0][row] = v.x;
            As[c4 * 4 + 1][row] = v.y;
            As[c4 * 4 + 2][row] = v.z;
            As[c4 * 4 + 3][row] = v.w;
        }
        {
            int row = tid >> 4;
            int c4  = tid & 15;
            float4 v = *(const float4*)(cow + (size_t)(kk + row) * Dh + n0 + c4 * 4);
            *(float4*)&Bs[row][c4 * 4] = v;
        }
        __syncthreads();

#pragma unroll
        for (int k = 0; k < BK; k++) {
            // a pairs: adjacent rows are contiguous in As -> LDS.64
            unsigned long long a2[4];
#pragma unroll
            for (int i = 0; i < 4; i++)
                a2[i] = *(const unsigned long long*)&As[k][ty * 8 + 2 * i];
            float bv[4];
#pragma unroll
            for (int j = 0; j < 4; j++) bv[j] = Bs[k][tx * 4 + j];
            unsigned long long b2[4];
#pragma unroll
            for (int j = 0; j < 4; j++) b2[j] = pack2(bv[j]);
#pragma unroll
            for (int i = 0; i < 4; i++)
#pragma unroll
                for (int j = 0; j < 4; j++)
                    acc2[i][j] = fma2(a2[i], b2[j], acc2[i][j]);
        }
        __syncthreads();
    }

#pragma unroll
    for (int i = 0; i < 4; i++) {
#pragma unroll
        for (int h = 0; h < 2; h++) {
            size_t row = (size_t)(m0 + ty * 8 + 2 * i + h) * Dh + n0 + tx * 4;
#pragma unroll
            for (int j = 0; j < 4; j++) {
                float lo, hi;
                asm("mov.b64 {%0, %1}, %2;" : "=f"(lo), "=f"(hi) : "l"(acc2[i][j]));
                g_cw[row + j] = h ? hi : lo;
            }
        }
    }
}

// ---------------------------------------------------------------------------
// Kernel 2: fused co-attention. One CTA per sample, 4 warps, 3 CTAs/SM.
// All per-lane operands register-resident; next z row prefetched to L1 via
// prefetch.global.L1 (zero register cost). Lane owns d = q*128 + lane*4 + j.
// ---------------------------------------------------------------------------
__global__ __launch_bounds__(128, 3) void fused_coattn_kernel(
    const float* __restrict__ text,
    const float* __restrict__ img,
    const float* __restrict__ comment,
    const int*   __restrict__ comment_num,
    const float* __restrict__ W_ca,
    const float* __restrict__ b_ca,
    const float* __restrict__ W_co,
    const float* __restrict__ b_co,
    float* __restrict__ out)
{
    const int b    = blockIdx.x;
    const int tid  = threadIdx.x;
    const int lane = tid & 31;
    const int warp = tid >> 5;
    const int loff = lane * 4;            // lane's base within each 128-chunk

    __shared__ float sbuf[4 * Dh];        // 8 KB staging
    __shared__ float rA[Dh], rB[Dh], rC[Dh];
    __shared__ float swr[4];
    __shared__ float pr[8];
    __shared__ float sscal[3];

    int cn = comment_num[b];
    if (cn > Ncm) cn = Ncm;
    if (cn < 1)   cn = 1;

    const float* tp  = text + (size_t)b * Dh;
    const float* ip  = img  + (size_t)b * Dh;
    const float* w0p = g_cw + (size_t)(2 * b) * Dh;
    const float* w1p = w0p + Dh;

    // register-resident per-lane operands (d = q*128 + lane*4 + j)
    float w0r[16], w1r[16], c0[16], c1[16], wco[16];
#pragma unroll
    for (int q = 0; q < 4; q++) {
        ((float4*)w0r)[q] = *(const float4*)(w0p + q * 128 + loff);
        ((float4*)w1r)[q] = *(const float4*)(w1p + q * 128 + loff);
        ((float4*)c0)[q]  = *(const float4*)(tp  + q * 128 + loff);
        ((float4*)c1)[q]  = *(const float4*)(ip  + q * 128 + loff);
        ((float4*)wco)[q] = *(const float4*)(W_co + q * 128 + loff);
    }

    float caA[16], caB[16], accv[16];
#pragma unroll
    for (int i = 0; i < 16; i++) { caA[i] = 0.f; caB[i] = 0.f; accv[i] = 0.f; }
    float ssum = 0.0f;
    const float bco = b_co[0];

    const float* cbase = comment + (size_t)b * Ncm * Dh + loff;

    // warm L1 for the first two rows this warp will touch
    if (warp < cn) {
#pragma unroll
        for (int q = 0; q < 4; q++)
            asm volatile("prefetch.global.L1 [%0];" ::
                         "l"(cbase + (size_t)warp * Dh + q * 128));
    }
    if (warp + 4 < cn) {
#pragma unroll
        for (int q = 0; q < 4; q++)
            asm volatile("prefetch.global.L1 [%0];" ::
                         "l"(cbase + (size_t)(warp + 4) * Dh + q * 128));
    }

    for (int n = warp; n < cn; n += 4) {
        const float* crow = cbase + (size_t)n * Dh;
        float z[16];
#pragma unroll
        for (int q = 0; q < 4; q++)
            ((float4*)z)[q] = *(const float4*)(crow + q * 128);

        // prefetch the row two iterations ahead
        if (n + 8 < cn) {
            const float* prow = cbase + (size_t)(n + 8) * Dh;
#pragma unroll
            for (int q = 0; q < 4; q++)
                asm volatile("prefetch.global.L1 [%0];" :: "l"(prow + q * 128));
        }

        // co_w[k,n] = tanh(cw[k] . z[n])
        float d0 = 0.f, d1 = 0.f;
#pragma unroll
        for (int i = 0; i < 16; i++) { d0 += w0r[i] * z[i]; d1 += w1r[i] * z[i]; }
#pragma unroll
        for (int o = 16; o > 0; o >>= 1) {
            d0 += __shfl_xor_sync(0xffffffffu, d0, o);
            d1 += __shfl_xor_sync(0xffffffffu, d1, o);
        }
        float co0 = fast_tanh(d0);
        float co1 = fast_tanh(d1);

        // accumulate co_w*z ; comment logit partial
        float pd = 0.f;
#pragma unroll
        for (int i = 0; i < 16; i++) {
            caA[i] += co0 * z[i];
            caB[i] += co1 * z[i];
            float t = fast_tanh(z[i] + co0 * c0[i] + co1 * c1[i]);
            pd += t * wco[i];
        }
#pragma unroll
        for (int o = 16; o > 0; o >>= 1)
            pd += __shfl_xor_sync(0xffffffffu, pd, o);

        // |logit| <= ||W_co||_1 ~ 18, raw exp safe in fp32.
        float e = __expf(pd + bco);
        ssum += e;
#pragma unroll
        for (int i = 0; i < 16; i++) accv[i] += e * z[i];
    }

    // ---- cross-warp reductions via smem (3 passes over one staging buffer) ----
    if (lane == 0) swr[warp] = ssum;

#pragma unroll
    for (int q = 0; q < 4; q++)
        *(float4*)&sbuf[warp * Dh + q * 128 + loff] = ((float4*)caA)[q];
    __syncthreads();
    for (int d = tid; d < Dh; d += 128) {
        float s = 0.f;
#pragma unroll
        for (int w = 0; w < 4; w++) s += sbuf[w * Dh + d];
        rA[d] = s;
    }
    __syncthreads();
#pragma unroll
    for (int q = 0; q < 4; q++)
        *(float4*)&sbuf[warp * Dh + q * 128 + loff] = ((float4*)caB)[q];
    __syncthreads();
    for (int d = tid; d < Dh; d += 128) {
        float s = 0.f;
#pragma unroll
        for (int w = 0; w < 4; w++) s += sbuf[w * Dh + d];
        rB[d] = s;
    }
    __syncthreads();
#pragma unroll
    for (int q = 0; q < 4; q++)
        *(float4*)&sbuf[warp * Dh + q * 128 + loff] = ((float4*)accv)[q];
    __syncthreads();
    for (int d = tid; d < Dh; d += 128) {
        float s = 0.f;
#pragma unroll
        for (int w = 0; w < 4; w++) s += sbuf[w * Dh + d];
        rC[d] = s;
    }
    __syncthreads();

    // ---- content attention logits ----
    float p0 = 0.f, p1 = 0.f;
    for (int d = tid; d < Dh; d += 128) {
        float wa = W_ca[d];
        p0 += fast_tanh(tp[d] + rA[d]) * wa;
        p1 += fast_tanh(ip[d] + rB[d]) * wa;
    }
#pragma unroll
    for (int o = 16; o > 0; o >>= 1) {
        p0 += __shfl_xor_sync(0xffffffffu, p0, o);
        p1 += __shfl_xor_sync(0xffffffffu, p1, o);
    }
    if (lane == 0) { pr[warp] = p0; pr[4 + warp] = p1; }
    __syncthreads();

    if (tid == 0) {
        float bca = b_ca[0];
        float l0 = bca, l1 = bca;
#pragma unroll
        for (int w = 0; w < 4; w++) { l0 += pr[w]; l1 += pr[4 + w]; }
        float mx = fmaxf(l0, l1);
        float e0 = __expf(l0 - mx), e1 = __expf(l1 - mx);
        float inv = __fdividef(1.0f, e0 + e1);
        float st = 0.f;
#pragma unroll
        for (int w = 0; w < 4; w++) st += swr[w];
        sscal[0] = e0 * inv;
        sscal[1] = e1 * inv;
        sscal[2] = __fdividef(1.0f, st);
    }
    __syncthreads();

    const float cwt0 = sscal[0], cwt1 = sscal[1], invs = sscal[2];
    for (int d = tid; d < Dh; d += 128) {
        out[(size_t)b * Dh + d]         = tp[d] * cwt0 + ip[d] * cwt1;
        out[(size_t)(Bsz + b) * Dh + d] = rC[d] * invs;
    }
    if (tid == 0) {
        out[(size_t)2 * Bsz * Dh + 2 * b]     = cwt0;
        out[(size_t)2 * Bsz * Dh + 2 * b + 1] = cwt1;
    }
}

// ---------------------------------------------------------------------------
extern "C" void kernel_launch(void* const* d_in, const int* in_sizes, int n_in,
                              void* d_out, int out_size)
{
    const float* text    = (const float*)d_in[0];
    const float* img     = (const float*)d_in[1];
    const float* comment = (const float*)d_in[2];
    const int*   cnum    = (const int*)d_in[3];
    const float* cow     = (const float*)d_in[4];
    const float* W_ca    = (const float*)d_in[5];
    const float* b_ca    = (const float*)d_in[6];
    const float* W_co    = (const float*)d_in[7];
    const float* b_co    = (const float*)d_in[8];
    float* out = (float*)d_out;

    dim3 ggrid(Dh / BN, (2 * Bsz) / BM);   // (8, 32)
    gemm_cw_kernel<<<ggrid, 256>>>(text, img, cow);
    fused_coattn_kernel<<<Bsz, 128>>>(text, img, comment, cnum,
                                      W_ca, b_ca, W_co, b_co, out);
}

// round 9
// speedup vs baseline: 1.6890x; 1.0333x over previous
#include <cuda_runtime.h>

#define Bsz 2048
#define Ncm 128
#define Dh  512

// 8MB scratch for cw = content @ cow  (rows interleaved: m = 2*b + k)
__device__ float g_cw[2 * Bsz * Dh];

__device__ __forceinline__ float fast_tanh(float x) {
    float y;
    asm("tanh.approx.f32 %0, %1;" : "=f"(y) : "f"(x));
    return y;
}

__device__ __forceinline__ unsigned long long fma2(unsigned long long a,
                                                   unsigned long long b,
                                                   unsigned long long c) {
    unsigned long long d;
    asm("fma.rn.f32x2 %0, %1, %2, %3;" : "=l"(d) : "l"(a), "l"(b), "l"(c));
    return d;
}

__device__ __forceinline__ unsigned long long mkpair(float x, float y) {
    unsigned long long r;
    asm("mov.b64 %0, {%1, %2};" : "=l"(r) : "f"(x), "f"(y));
    return r;
}

// ---------------------------------------------------------------------------
// Kernel 1: cw[m, e] = sum_d A[m, d] * cow[d, e]
//   M = 2*Bsz = 4096, N = K = 512.  BM=128, BN=128, BK=8, 256 threads,
//   8x8 per thread. f32x2 accumulators paired along N (adjacent cols), so
//   B pairs come straight from LDS.128; A stored duplicated ({a,a} float2)
//   so one LDS.128 yields two rows' broadcast pairs. Gmem for the next
//   K-chunk is prefetched into registers before computing the current one.
// ---------------------------------------------------------------------------
#define GBM 128
#define GBN 128
#define GBK 8

__global__ __launch_bounds__(256) void gemm_cw_kernel(
    const float* __restrict__ text,
    const float* __restrict__ img,
    const float* __restrict__ cow)
{
    __shared__ float2 As2[GBK][GBM];   // duplicated pairs {a,a}  (8 KB)
    __shared__ float  Bs[GBK][GBN];    // (4 KB)

    const int tid = threadIdx.x;
    const int m0 = blockIdx.y * GBM;
    const int n0 = blockIdx.x * GBN;
    const int ty = tid >> 4;   // 0..15 -> row group of 8
    const int tx = tid & 15;   // 0..15 -> col group of 8

    // A load mapping: row ar (0..127), half ah selects 4 of the 8 k's
    const int ar = tid >> 1;
    const int ah = tid & 1;
    const int am = m0 + ar;
    const float* asrc = ((am & 1) ? img : text) + (size_t)(am >> 1) * Dh;
    // B load mapping: k-row bk (0..7), float4 column bc (0..31)
    const int bk = tid >> 5;
    const int bc = tid & 31;

    unsigned long long acc2[8][4];     // [row][col-pair]
#pragma unroll
    for (int i = 0; i < 8; i++)
#pragma unroll
        for (int j = 0; j < 4; j++) acc2[i][j] = 0ull;

    float4 aReg = *(const float4*)(asrc + ah * 4);
    float4 bReg = *(const float4*)(cow + (size_t)bk * Dh + n0 + bc * 4);

    for (int kk = 0; kk < Dh; kk += GBK) {
        // stage current chunk from registers
        As2[ah * 4 + 0][ar] = make_float2(aReg.x, aReg.x);
        As2[ah * 4 + 1][ar] = make_float2(aReg.y, aReg.y);
        As2[ah * 4 + 2][ar] = make_float2(aReg.z, aReg.z);
        As2[ah * 4 + 3][ar] = make_float2(aReg.w, aReg.w);
        *(float4*)&Bs[bk][bc * 4] = bReg;
        __syncthreads();

        // prefetch next chunk into registers (hidden behind compute below)
        if (kk + GBK < Dh) {
            aReg = *(const float4*)(asrc + kk + GBK + ah * 4);
            bReg = *(const float4*)(cow + (size_t)(kk + GBK + bk) * Dh + n0 + bc * 4);
        }

#pragma unroll
        for (int k = 0; k < GBK; k++) {
            ulonglong2 ap[4];
#pragma unroll
            for (int i = 0; i < 4; i++)
                ap[i] = *(const ulonglong2*)&As2[k][ty * 8 + 2 * i];
            float4 b0 = *(const float4*)&Bs[k][tx * 8];
            float4 b1 = *(const float4*)&Bs[k][tx * 8 + 4];
            unsigned long long bp[4];
            bp[0] = mkpair(b0.x, b0.y);
            bp[1] = mkpair(b0.z, b0.w);
            bp[2] = mkpair(b1.x, b1.y);
            bp[3] = mkpair(b1.z, b1.w);
#pragma unroll
            for (int i = 0; i < 8; i++) {
                unsigned long long av = (i & 1) ? ap[i >> 1].y : ap[i >> 1].x;
#pragma unroll
                for (int j = 0; j < 4; j++)
                    acc2[i][j] = fma2(av, bp[j], acc2[i][j]);
            }
        }
        __syncthreads();
    }

    // epilogue: row-pairs of adjacent columns are already contiguous
#pragma unroll
    for (int i = 0; i < 8; i++) {
        float* dst = g_cw + (size_t)(m0 + ty * 8 + i) * Dh + n0 + tx * 8;
        ulonglong2 s0; s0.x = acc2[i][0]; s0.y = acc2[i][1];
        ulonglong2 s1; s1.x = acc2[i][2]; s1.y = acc2[i][3];
        *(ulonglong2*)dst       = s0;
        *(ulonglong2*)(dst + 4) = s1;
    }
}

// ---------------------------------------------------------------------------
// Kernel 2: fused co-attention. One CTA per sample, 4 warps, 4 CTAs/SM.
// c0/c1 + accumulators register-resident; w0/w1/wco in shared memory to fit
// under 128 regs. Next z row prefetched to L1. Lane owns d = q*128+lane*4+j.
// ---------------------------------------------------------------------------
__global__ __launch_bounds__(128, 4) void fused_coattn_kernel(
    const float* __restrict__ text,
    const float* __restrict__ img,
    const float* __restrict__ comment,
    const int*   __restrict__ comment_num,
    const float* __restrict__ W_ca,
    const float* __restrict__ b_ca,
    const float* __restrict__ W_co,
    const float* __restrict__ b_co,
    float* __restrict__ out)
{
    const int b    = blockIdx.x;
    const int tid  = threadIdx.x;
    const int lane = tid & 31;
    const int warp = tid >> 5;
    const int loff = lane * 4;            // lane's base within each 128-chunk

    __shared__ float sw0[Dh], sw1[Dh], swco[Dh];   // 6 KB
    __shared__ float sbuf[4 * Dh];                 // 8 KB staging
    __shared__ float rA[Dh], rB[Dh], rC[Dh];       // 6 KB
    __shared__ float swr[4];
    __shared__ float pr[8];
    __shared__ float sscal[3];

    int cn = comment_num[b];
    if (cn > Ncm) cn = Ncm;
    if (cn < 1)   cn = 1;

    const float* tp  = text + (size_t)b * Dh;
    const float* ip  = img  + (size_t)b * Dh;
    const float* w0p = g_cw + (size_t)(2 * b) * Dh;
    const float* w1p = w0p + Dh;

    // shared operands (cooperative fill)
    for (int d = tid * 4; d < Dh; d += 128 * 4) {
        *(float4*)&sw0[d]  = *(const float4*)(w0p + d);
        *(float4*)&sw1[d]  = *(const float4*)(w1p + d);
        *(float4*)&swco[d] = *(const float4*)(W_co + d);
    }
    // register-resident per-lane operands
    float c0[16], c1[16];
#pragma unroll
    for (int q = 0; q < 4; q++) {
        ((float4*)c0)[q] = *(const float4*)(tp + q * 128 + loff);
        ((float4*)c1)[q] = *(const float4*)(ip + q * 128 + loff);
    }
    __syncthreads();

    float caA[16], caB[16], accv[16];
#pragma unroll
    for (int i = 0; i < 16; i++) { caA[i] = 0.f; caB[i] = 0.f; accv[i] = 0.f; }
    float ssum = 0.0f;
    const float bco = b_co[0];

    const float* cbase = comment + (size_t)b * Ncm * Dh + loff;

    // warm L1 for the first two rows this warp touches
    if (warp < cn) {
#pragma unroll
        for (int q = 0; q < 4; q++)
            asm volatile("prefetch.global.L1 [%0];" ::
                         "l"(cbase + (size_t)warp * Dh + q * 128));
    }
    if (warp + 4 < cn) {
#pragma unroll
        for (int q = 0; q < 4; q++)
            asm volatile("prefetch.global.L1 [%0];" ::
                         "l"(cbase + (size_t)(warp + 4) * Dh + q * 128));
    }

    for (int n = warp; n < cn; n += 4) {
        const float* crow = cbase + (size_t)n * Dh;
        float z[16];
#pragma unroll
        for (int q = 0; q < 4; q++)
            ((float4*)z)[q] = *(const float4*)(crow + q * 128);

        if (n + 8 < cn) {
            const float* prow = cbase + (size_t)(n + 8) * Dh;
#pragma unroll
            for (int q = 0; q < 4; q++)
                asm volatile("prefetch.global.L1 [%0];" :: "l"(prow + q * 128));
        }

        // co_w[k,n] = tanh(cw[k] . z[n])
        float d0 = 0.f, d1 = 0.f;
#pragma unroll
        for (int q = 0; q < 4; q++) {
            float4 a0 = *(const float4*)&sw0[q * 128 + loff];
            float4 a1 = *(const float4*)&sw1[q * 128 + loff];
            const float* zq = z + q * 4;
            d0 += a0.x * zq[0] + a0.y * zq[1] + a0.z * zq[2] + a0.w * zq[3];
            d1 += a1.x * zq[0] + a1.y * zq[1] + a1.z * zq[2] + a1.w * zq[3];
        }
#pragma unroll
        for (int o = 16; o > 0; o >>= 1) {
            d0 += __shfl_xor_sync(0xffffffffu, d0, o);
            d1 += __shfl_xor_sync(0xffffffffu, d1, o);
        }
        float co0 = fast_tanh(d0);
        float co1 = fast_tanh(d1);

        // accumulate co_w*z ; comment logit partial
        float pd = 0.f;
#pragma unroll
        for (int q = 0; q < 4; q++) {
            float4 wv = *(const float4*)&swco[q * 128 + loff];
            const float wj[4] = {wv.x, wv.y, wv.z, wv.w};
#pragma unroll
            for (int j = 0; j < 4; j++) {
                int i = q * 4 + j;
                caA[i] += co0 * z[i];
                caB[i] += co1 * z[i];
                float t = fast_tanh(z[i] + co0 * c0[i] + co1 * c1[i]);
                pd += t * wj[j];
            }
        }
#pragma unroll
        for (int o = 16; o > 0; o >>= 1)
            pd += __shfl_xor_sync(0xffffffffu, pd, o);

        // |logit| <= ||W_co||_1 ~ 18, raw exp safe in fp32.
        float e = __expf(pd + bco);
        ssum += e;
#pragma unroll
        for (int i = 0; i < 16; i++) accv[i] += e * z[i];
    }

    // ---- cross-warp reductions via smem (3 passes over one staging buffer) ----
    if (lane == 0) swr[warp] = ssum;

#pragma unroll
    for (int q = 0; q < 4; q++)
        *(float4*)&sbuf[warp * Dh + q * 128 + loff] = ((float4*)caA)[q];
    __syncthreads();
    for (int d = tid; d < Dh; d += 128) {
        float s = 0.f;
#pragma unroll
        for (int w = 0; w < 4; w++) s += sbuf[w * Dh + d];
        rA[d] = s;
    }
    __syncthreads();
#pragma unroll
    for (int q = 0; q < 4; q++)
        *(float4*)&sbuf[warp * Dh + q * 128 + loff] = ((float4*)caB)[q];
    __syncthreads();
    for (int d = tid; d < Dh; d += 128) {
        float s = 0.f;
#pragma unroll
        for (int w = 0; w < 4; w++) s += sbuf[w * Dh + d];
        rB[d] = s;
    }
    __syncthreads();
#pragma unroll
    for (int q = 0; q < 4; q++)
        *(float4*)&sbuf[warp * Dh + q * 128 + loff] = ((float4*)accv)[q];
    __syncthreads();
    for (int d = tid; d < Dh; d += 128) {
        float s = 0.f;
#pragma unroll
        for (int w = 0; w < 4; w++) s += sbuf[w * Dh + d];
        rC[d] = s;
    }
    __syncthreads();

    // ---- content attention logits ----
    float p0 = 0.f, p1 = 0.f;
    for (int d = tid; d < Dh; d += 128) {
        float wa = W_ca[d];
        p0 += fast_tanh(tp[d] + rA[d]) * wa;
        p1 += fast_tanh(ip[d] + rB[d]) * wa;
    }
#pragma unroll
    for (int o = 16; o > 0; o >>= 1) {
        p0 += __shfl_xor_sync(0xffffffffu, p0, o);
        p1 += __shfl_xor_sync(0xffffffffu, p1, o);
    }
    if (lane == 0) { pr[warp] = p0; pr[4 + warp] = p1; }
    __syncthreads();

    if (tid == 0) {
        float bca = b_ca[0];
        float l0 = bca, l1 = bca;
#pragma unroll
        for (int w = 0; w < 4; w++) { l0 += pr[w]; l1 += pr[4 + w]; }
        float mx = fmaxf(l0, l1);
        float e0 = __expf(l0 - mx), e1 = __expf(l1 - mx);
        float inv = __fdividef(1.0f, e0 + e1);
        float st = 0.f;
#pragma unroll
        for (int w = 0; w < 4; w++) st += swr[w];
        sscal[0] = e0 * inv;
        sscal[1] = e1 * inv;
        sscal[2] = __fdividef(1.0f, st);
    }
    __syncthreads();

    const float cwt0 = sscal[0], cwt1 = sscal[1], invs = sscal[2];
    for (int d = tid; d < Dh; d += 128) {
        out[(size_t)b * Dh + d]         = tp[d] * cwt0 + ip[d] * cwt1;
        out[(size_t)(Bsz + b) * Dh + d] = rC[d] * invs;
    }
    if (tid == 0) {
        out[(size_t)2 * Bsz * Dh + 2 * b]     = cwt0;
        out[(size_t)2 * Bsz * Dh + 2 * b + 1] = cwt1;
    }
}

// ---------------------------------------------------------------------------
extern "C" void kernel_launch(void* const* d_in, const int* in_sizes, int n_in,
                              void* d_out, int out_size)
{
    const float* text    = (const float*)d_in[0];
    const float* img     = (const float*)d_in[1];
    const float* comment = (const float*)d_in[2];
    const int*   cnum    = (const int*)d_in[3];
    const float* cow     = (const float*)d_in[4];
    const float* W_ca    = (const float*)d_in[5];
    const float* b_ca    = (const float*)d_in[6];
    const float* W_co    = (const float*)d_in[7];
    const float* b_co    = (const float*)d_in[8];
    float* out = (float*)d_out;

    dim3 ggrid(Dh / GBN, (2 * Bsz) / GBM);   // (4, 32) = 128 CTAs
    gemm_cw_kernel<<<ggrid, 256>>>(text, img, cow);
    fused_coattn_kernel<<<Bsz, 128>>>(text, img, comment, cnum,
                                      W_ca, b_ca, W_co, b_co, out);
}

// round 10
// speedup vs baseline: 2.0095x; 1.1898x over previous
#include <cuda_runtime.h>

#define Bsz 2048
#define Ncm 128
#define Dh  512

// 8MB scratch for cw = content @ cow  (rows interleaved: m = 2*b + k)
__device__ float g_cw[2 * Bsz * Dh];

__device__ __forceinline__ float fast_tanh(float x) {
    float y;
    asm("tanh.approx.f32 %0, %1;" : "=f"(y) : "f"(x));
    return y;
}

__device__ __forceinline__ unsigned int to_tf32(float v) {
    unsigned int r;
    asm("cvt.rna.tf32.f32 %0, %1;" : "=r"(r) : "f"(v));
    return r;
}

__device__ __forceinline__ void mma_tf32(float& c0, float& c1, float& c2, float& c3,
                                         unsigned int a0, unsigned int a1,
                                         unsigned int a2, unsigned int a3,
                                         unsigned int b0, unsigned int b1) {
    asm("mma.sync.aligned.m16n8k8.row.col.f32.tf32.tf32.f32 "
        "{%0,%1,%2,%3}, {%4,%5,%6,%7}, {%8,%9}, {%0,%1,%2,%3};"
        : "+f"(c0), "+f"(c1), "+f"(c2), "+f"(c3)
        : "r"(a0), "r"(a1), "r"(a2), "r"(a3), "r"(b0), "r"(b1));
}

// ---------------------------------------------------------------------------
// Kernel 1: cw[m, e] = sum_d A[m, d] * cow[d, e]   — tf32 tensor-core GEMM
// with 3xTF32 split (aH*bH + aH*bL + aL*bH) for ~fp32 accuracy.
//   M = 4096, N = K = 512. CTA tile 128x128, BK=16, 256 threads = 8 warps
//   (2 M x 4 N), warp tile 64x32 of m16n8k8 fragments.
// ---------------------------------------------------------------------------
#define TM 128
#define TN 128
#define TK 16
#define APITCH (TK + 4)    // 20 floats  -> conflict-free A frag loads
#define BPITCH (TN + 8)    // 136 floats -> conflict-free B frag loads

__global__ __launch_bounds__(256) void gemm_cw_kernel(
    const float* __restrict__ text,
    const float* __restrict__ img,
    const float* __restrict__ cow)
{
    __shared__ unsigned int AsH[TM * APITCH];
    __shared__ unsigned int AsL[TM * APITCH];
    __shared__ unsigned int BsH[TK * BPITCH];
    __shared__ unsigned int BsL[TK * BPITCH];

    const int tid = threadIdx.x;
    const int m0g = blockIdx.y * TM;
    const int n0g = blockIdx.x * TN;

    const int warp = tid >> 5;
    const int lane = tid & 31;
    const int wm = warp & 1;        // 0..1  -> warp M origin wm*64
    const int wn = warp >> 1;       // 0..3  -> warp N origin wn*32
    const int g  = lane >> 2;       // groupID
    const int t  = lane & 3;        // threadID_in_group

    // global load mapping
    const int ar = tid >> 1;        // A row 0..127
    const int ah = tid & 1;         // A col half: 8 floats
    const int am = m0g + ar;
    const float* asrc = ((am & 1) ? img : text) + (size_t)(am >> 1) * Dh + ah * 8;
    const int bk = tid >> 4;        // B row 0..15
    const int bc = tid & 15;        // B col group: 8 floats
    const float* bsrc = cow + (size_t)bk * Dh + n0g + bc * 8;

    float acc[4][4][4];             // [mfrag][nfrag][c0..c3]
#pragma unroll
    for (int f = 0; f < 4; f++)
#pragma unroll
        for (int j = 0; j < 4; j++)
#pragma unroll
            for (int c = 0; c < 4; c++) acc[f][j][c] = 0.0f;

    float4 aR0 = *(const float4*)(asrc);
    float4 aR1 = *(const float4*)(asrc + 4);
    float4 bR0 = *(const float4*)(bsrc);
    float4 bR1 = *(const float4*)(bsrc + 4);

    for (int kk = 0; kk < Dh; kk += TK) {
        // ---- split + stage current chunk ----
        {
            float av[8] = {aR0.x, aR0.y, aR0.z, aR0.w, aR1.x, aR1.y, aR1.z, aR1.w};
            unsigned int hi[8], lo[8];
#pragma unroll
            for (int i = 0; i < 8; i++) {
                hi[i] = to_tf32(av[i]);
                lo[i] = to_tf32(av[i] - __uint_as_float(hi[i]));
            }
            unsigned int* pH = &AsH[ar * APITCH + ah * 8];
            unsigned int* pL = &AsL[ar * APITCH + ah * 8];
            *(uint4*)pH       = make_uint4(hi[0], hi[1], hi[2], hi[3]);
            *(uint4*)(pH + 4) = make_uint4(hi[4], hi[5], hi[6], hi[7]);
            *(uint4*)pL       = make_uint4(lo[0], lo[1], lo[2], lo[3]);
            *(uint4*)(pL + 4) = make_uint4(lo[4], lo[5], lo[6], lo[7]);

            float bv[8] = {bR0.x, bR0.y, bR0.z, bR0.w, bR1.x, bR1.y, bR1.z, bR1.w};
#pragma unroll
            for (int i = 0; i < 8; i++) {
                hi[i] = to_tf32(bv[i]);
                lo[i] = to_tf32(bv[i] - __uint_as_float(hi[i]));
            }
            unsigned int* qH = &BsH[bk * BPITCH + bc * 8];
            unsigned int* qL = &BsL[bk * BPITCH + bc * 8];
            *(uint4*)qH       = make_uint4(hi[0], hi[1], hi[2], hi[3]);
            *(uint4*)(qH + 4) = make_uint4(hi[4], hi[5], hi[6], hi[7]);
            *(uint4*)qL       = make_uint4(lo[0], lo[1], lo[2], lo[3]);
            *(uint4*)(qL + 4) = make_uint4(lo[4], lo[5], lo[6], lo[7]);
        }
        __syncthreads();

        // ---- prefetch next chunk ----
        if (kk + TK < Dh) {
            aR0 = *(const float4*)(asrc + kk + TK);
            aR1 = *(const float4*)(asrc + kk + TK + 4);
            bR0 = *(const float4*)(bsrc + (size_t)TK * Dh + kk * 1 + 0);  // placeholder, fixed below
        }
        // (B advances along K by rows: row bk of chunk kk+TK is cow[kk+TK+bk])
        if (kk + TK < Dh) {
            const float* bnext = cow + (size_t)(kk + TK + bk) * Dh + n0g + bc * 8;
            bR0 = *(const float4*)(bnext);
            bR1 = *(const float4*)(bnext + 4);
        }

        // ---- compute: 2 k-steps of m16n8k8, 3 passes each ----
#pragma unroll
        for (int ks = 0; ks < 2; ks++) {
            const int k0 = ks * 8;
            unsigned int aH[4][4], aL[4][4];
#pragma unroll
            for (int f = 0; f < 4; f++) {
                int r0 = (wm * 64 + f * 16 + g) * APITCH + k0 + t;
                int r1 = r0 + 8 * APITCH;
                aH[f][0] = AsH[r0];     aH[f][1] = AsH[r1];
                aH[f][2] = AsH[r0 + 4]; aH[f][3] = AsH[r1 + 4];
                aL[f][0] = AsL[r0];     aL[f][1] = AsL[r1];
                aL[f][2] = AsL[r0 + 4]; aL[f][3] = AsL[r1 + 4];
            }
            unsigned int bH[4][2], bL[4][2];
#pragma unroll
            for (int j = 0; j < 4; j++) {
                int c0i = (k0 + t) * BPITCH + wn * 32 + j * 8 + g;
                int c1i = c0i + 4 * BPITCH;
                bH[j][0] = BsH[c0i]; bH[j][1] = BsH[c1i];
                bL[j][0] = BsL[c0i]; bL[j][1] = BsL[c1i];
            }
#pragma unroll
            for (int f = 0; f < 4; f++)
#pragma unroll
                for (int j = 0; j < 4; j++) {
                    mma_tf32(acc[f][j][0], acc[f][j][1], acc[f][j][2], acc[f][j][3],
                             aH[f][0], aH[f][1], aH[f][2], aH[f][3], bH[j][0], bH[j][1]);
                    mma_tf32(acc[f][j][0], acc[f][j][1], acc[f][j][2], acc[f][j][3],
                             aH[f][0], aH[f][1], aH[f][2], aH[f][3], bL[j][0], bL[j][1]);
                    mma_tf32(acc[f][j][0], acc[f][j][1], acc[f][j][2], acc[f][j][3],
                             aL[f][0], aL[f][1], aL[f][2], aL[f][3], bH[j][0], bH[j][1]);
                }
        }
        __syncthreads();
    }

    // ---- epilogue ----
#pragma unroll
    for (int f = 0; f < 4; f++) {
        int row0 = m0g + wm * 64 + f * 16 + g;
#pragma unroll
        for (int j = 0; j < 4; j++) {
            int col = n0g + wn * 32 + j * 8 + 2 * t;
            *(float2*)&g_cw[(size_t)row0 * Dh + col] =
                make_float2(acc[f][j][0], acc[f][j][1]);
            *(float2*)&g_cw[(size_t)(row0 + 8) * Dh + col] =
                make_float2(acc[f][j][2], acc[f][j][3]);
        }
    }
}

// ---------------------------------------------------------------------------
// Kernel 2: fused co-attention (unchanged from round 9).
// One CTA per sample, 4 warps, 4 CTAs/SM. c0/c1 + accumulators in registers;
// w0/w1/wco in shared. Next z row prefetched to L1.
// ---------------------------------------------------------------------------
__global__ __launch_bounds__(128, 4) void fused_coattn_kernel(
    const float* __restrict__ text,
    const float* __restrict__ img,
    const float* __restrict__ comment,
    const int*   __restrict__ comment_num,
    const float* __restrict__ W_ca,
    const float* __restrict__ b_ca,
    const float* __restrict__ W_co,
    const float* __restrict__ b_co,
    float* __restrict__ out)
{
    const int b    = blockIdx.x;
    const int tid  = threadIdx.x;
    const int lane = tid & 31;
    const int warp = tid >> 5;
    const int loff = lane * 4;

    __shared__ float sw0[Dh], sw1[Dh], swco[Dh];
    __shared__ float sbuf[4 * Dh];
    __shared__ float rA[Dh], rB[Dh], rC[Dh];
    __shared__ float swr[4];
    __shared__ float pr[8];
    __shared__ float sscal[3];

    int cn = comment_num[b];
    if (cn > Ncm) cn = Ncm;
    if (cn < 1)   cn = 1;

    const float* tp  = text + (size_t)b * Dh;
    const float* ip  = img  + (size_t)b * Dh;
    const float* w0p = g_cw + (size_t)(2 * b) * Dh;
    const float* w1p = w0p + Dh;

    for (int d = tid * 4; d < Dh; d += 128 * 4) {
        *(float4*)&sw0[d]  = *(const float4*)(w0p + d);
        *(float4*)&sw1[d]  = *(const float4*)(w1p + d);
        *(float4*)&swco[d] = *(const float4*)(W_co + d);
    }
    float c0[16], c1[16];
#pragma unroll
    for (int q = 0; q < 4; q++) {
        ((float4*)c0)[q] = *(const float4*)(tp + q * 128 + loff);
        ((float4*)c1)[q] = *(const float4*)(ip + q * 128 + loff);
    }
    __syncthreads();

    float caA[16], caB[16], accv[16];
#pragma unroll
    for (int i = 0; i < 16; i++) { caA[i] = 0.f; caB[i] = 0.f; accv[i] = 0.f; }
    float ssum = 0.0f;
    const float bco = b_co[0];

    const float* cbase = comment + (size_t)b * Ncm * Dh + loff;

    if (warp < cn) {
#pragma unroll
        for (int q = 0; q < 4; q++)
            asm volatile("prefetch.global.L1 [%0];" ::
                         "l"(cbase + (size_t)warp * Dh + q * 128));
    }
    if (warp + 4 < cn) {
#pragma unroll
        for (int q = 0; q < 4; q++)
            asm volatile("prefetch.global.L1 [%0];" ::
                         "l"(cbase + (size_t)(warp + 4) * Dh + q * 128));
    }

    for (int n = warp; n < cn; n += 4) {
        const float* crow = cbase + (size_t)n * Dh;
        float z[16];
#pragma unroll
        for (int q = 0; q < 4; q++)
            ((float4*)z)[q] = *(const float4*)(crow + q * 128);

        if (n + 8 < cn) {
            const float* prow = cbase + (size_t)(n + 8) * Dh;
#pragma unroll
            for (int q = 0; q < 4; q++)
                asm volatile("prefetch.global.L1 [%0];" :: "l"(prow + q * 128));
        }

        float d0 = 0.f, d1 = 0.f;
#pragma unroll
        for (int q = 0; q < 4; q++) {
            float4 a0 = *(const float4*)&sw0[q * 128 + loff];
            float4 a1 = *(const float4*)&sw1[q * 128 + loff];
            const float* zq = z + q * 4;
            d0 += a0.x * zq[0] + a0.y * zq[1] + a0.z * zq[2] + a0.w * zq[3];
            d1 += a1.x * zq[0] + a1.y * zq[1] + a1.z * zq[2] + a1.w * zq[3];
        }
#pragma unroll
        for (int o = 16; o > 0; o >>= 1) {
            d0 += __shfl_xor_sync(0xffffffffu, d0, o);
            d1 += __shfl_xor_sync(0xffffffffu, d1, o);
        }
        float co0 = fast_tanh(d0);
        float co1 = fast_tanh(d1);

        float pd = 0.f;
#pragma unroll
        for (int q = 0; q < 4; q++) {
            float4 wv = *(const float4*)&swco[q * 128 + loff];
            const float wj[4] = {wv.x, wv.y, wv.z, wv.w};
#pragma unroll
            for (int j = 0; j < 4; j++) {
                int i = q * 4 + j;
                caA[i] += co0 * z[i];
                caB[i] += co1 * z[i];
                float t = fast_tanh(z[i] + co0 * c0[i] + co1 * c1[i]);
                pd += t * wj[j];
            }
        }
#pragma unroll
        for (int o = 16; o > 0; o >>= 1)
            pd += __shfl_xor_sync(0xffffffffu, pd, o);

        float e = __expf(pd + bco);
        ssum += e;
#pragma unroll
        for (int i = 0; i < 16; i++) accv[i] += e * z[i];
    }

    if (lane == 0) swr[warp] = ssum;

#pragma unroll
    for (int q = 0; q < 4; q++)
        *(float4*)&sbuf[warp * Dh + q * 128 + loff] = ((float4*)caA)[q];
    __syncthreads();
    for (int d = tid; d < Dh; d += 128) {
        float s = 0.f;
#pragma unroll
        for (int w = 0; w < 4; w++) s += sbuf[w * Dh + d];
        rA[d] = s;
    }
    __syncthreads();
#pragma unroll
    for (int q = 0; q < 4; q++)
        *(float4*)&sbuf[warp * Dh + q * 128 + loff] = ((float4*)caB)[q];
    __syncthreads();
    for (int d = tid; d < Dh; d += 128) {
        float s = 0.f;
#pragma unroll
        for (int w = 0; w < 4; w++) s += sbuf[w * Dh + d];
        rB[d] = s;
    }
    __syncthreads();
#pragma unroll
    for (int q = 0; q < 4; q++)
        *(float4*)&sbuf[warp * Dh + q * 128 + loff] = ((float4*)accv)[q];
    __syncthreads();
    for (int d = tid; d < Dh; d += 128) {
        float s = 0.f;
#pragma unroll
        for (int w = 0; w < 4; w++) s += sbuf[w * Dh + d];
        rC[d] = s;
    }
    __syncthreads();

    float p0 = 0.f, p1 = 0.f;
    for (int d = tid; d < Dh; d += 128) {
        float wa = W_ca[d];
        p0 += fast_tanh(tp[d] + rA[d]) * wa;
        p1 += fast_tanh(ip[d] + rB[d]) * wa;
    }
#pragma unroll
    for (int o = 16; o > 0; o >>= 1) {
        p0 += __shfl_xor_sync(0xffffffffu, p0, o);
        p1 += __shfl_xor_sync(0xffffffffu, p1, o);
    }
    if (lane == 0) { pr[warp] = p0; pr[4 + warp] = p1; }
    __syncthreads();

    if (tid == 0) {
        float bca = b_ca[0];
        float l0 = bca, l1 = bca;
#pragma unroll
        for (int w = 0; w < 4; w++) { l0 += pr[w]; l1 += pr[4 + w]; }
        float mx = fmaxf(l0, l1);
        float e0 = __expf(l0 - mx), e1 = __expf(l1 - mx);
        float inv = __fdividef(1.0f, e0 + e1);
        float st = 0.f;
#pragma unroll
        for (int w = 0; w < 4; w++) st += swr[w];
        sscal[0] = e0 * inv;
        sscal[1] = e1 * inv;
        sscal[2] = __fdividef(1.0f, st);
    }
    __syncthreads();

    const float cwt0 = sscal[0], cwt1 = sscal[1], invs = sscal[2];
    for (int d = tid; d < Dh; d += 128) {
        out[(size_t)b * Dh + d]         = tp[d] * cwt0 + ip[d] * cwt1;
        out[(size_t)(Bsz + b) * Dh + d] = rC[d] * invs;
    }
    if (tid == 0) {
        out[(size_t)2 * Bsz * Dh + 2 * b]     = cwt0;
        out[(size_t)2 * Bsz * Dh + 2 * b + 1] = cwt1;
    }
}

// ---------------------------------------------------------------------------
extern "C" void kernel_launch(void* const* d_in, const int* in_sizes, int n_in,
                              void* d_out, int out_size)
{
    const float* text    = (const float*)d_in[0];
    const float* img     = (const float*)d_in[1];
    const float* comment = (const float*)d_in[2];
    const int*   cnum    = (const int*)d_in[3];
    const float* cow     = (const float*)d_in[4];
    const float* W_ca    = (const float*)d_in[5];
    const float* b_ca    = (const float*)d_in[6];
    const float* W_co    = (const float*)d_in[7];
    const float* b_co    = (const float*)d_in[8];
    float* out = (float*)d_out;

    dim3 ggrid(Dh / TN, (2 * Bsz) / TM);   // (4, 32) = 128 CTAs
    gemm_cw_kernel<<<ggrid, 256>>>(text, img, cow);
    fused_coattn_kernel<<<Bsz, 128>>>(text, img, comment, cnum,
                                      W_ca, b_ca, W_co, b_co, out);
}